// round 1
// baseline (speedup 1.0000x reference)
#include <cuda_runtime.h>
#include <math.h>

// Problem sizes (fixed by the reference)
#define BSZ 4096
#define ISZ 1024
#define HSZ 2048

#define BM 128
#define BN 128
#define BK 8
#define TM 8
#define TN 8
#define NTHREADS 256

// ---------------------------------------------------------------------------
// Kernel 1: z = [x|h] @ [wx; wh] + bias   (K = ISZ + HSZ = 3072, N = HSZ)
//   mode 0: out = tanh(z)                              (g_new)
//   mode 1: hc = tanh(z); out = g*hc + (1-g)*h         (h_new)
// ---------------------------------------------------------------------------
__global__ __launch_bounds__(NTHREADS) void rnn_gate_gemm(
    const float* __restrict__ x,   // [BSZ, ISZ]
    const float* __restrict__ h,   // [BSZ, HSZ]
    const float* __restrict__ wx,  // [ISZ, HSZ]
    const float* __restrict__ wh,  // [HSZ, HSZ]
    const float* __restrict__ bias,// [HSZ]
    const float* __restrict__ g,   // [BSZ, HSZ] (used only in mode 1)
    float* __restrict__ out,       // [BSZ, HSZ]
    int mode)
{
    __shared__ float As[BK][BM];
    __shared__ float Bs[BK][BN];

    const int tid = threadIdx.x;
    const int tx = tid & 15;        // 0..15 -> column group
    const int ty = tid >> 4;        // 0..15 -> row group
    const int rowBase = blockIdx.y * BM;
    const int colBase = blockIdx.x * BN;

    float acc[TM][TN];
#pragma unroll
    for (int i = 0; i < TM; i++)
#pragma unroll
        for (int j = 0; j < TN; j++) acc[i][j] = 0.0f;

    // A-tile loader: 128 rows x 8 cols, one float4 per thread
    const int aRow = tid >> 1;          // 0..127
    const int aK   = (tid & 1) * 4;     // 0 or 4
    // B-tile loader: 8 rows x 128 cols, one float4 per thread
    const int bK   = tid >> 5;          // 0..7
    const int bCol = (tid & 31) * 4;    // 0..124

    const int KTOT = ISZ + HSZ;         // 3072; boundary 1024 is BK-aligned
    for (int k0 = 0; k0 < KTOT; k0 += BK) {
        const float* Aptr;
        const float* Wptr;
        int lda, kk;
        if (k0 < ISZ) { Aptr = x; lda = ISZ; kk = k0;        Wptr = wx; }
        else          { Aptr = h; lda = HSZ; kk = k0 - ISZ;  Wptr = wh; }

        float4 av = *reinterpret_cast<const float4*>(
            &Aptr[(size_t)(rowBase + aRow) * lda + kk + aK]);
        As[aK + 0][aRow] = av.x;
        As[aK + 1][aRow] = av.y;
        As[aK + 2][aRow] = av.z;
        As[aK + 3][aRow] = av.w;

        float4 bv = *reinterpret_cast<const float4*>(
            &Wptr[(size_t)(kk + bK) * HSZ + colBase + bCol]);
        *reinterpret_cast<float4*>(&Bs[bK][bCol]) = bv;

        __syncthreads();

#pragma unroll
        for (int k = 0; k < BK; k++) {
            float a[TM], b[TN];
#pragma unroll
            for (int i = 0; i < TM; i++) a[i] = As[k][ty * TM + i];
#pragma unroll
            for (int j = 0; j < TN; j++) b[j] = Bs[k][tx * TN + j];
#pragma unroll
            for (int i = 0; i < TM; i++)
#pragma unroll
                for (int j = 0; j < TN; j++)
                    acc[i][j] = fmaf(a[i], b[j], acc[i][j]);
        }
        __syncthreads();
    }

    // Epilogue
#pragma unroll
    for (int i = 0; i < TM; i++) {
        const int row = rowBase + ty * TM + i;
#pragma unroll
        for (int j = 0; j < TN; j++) {
            const int col = colBase + tx * TN + j;
            const size_t idx = (size_t)row * HSZ + col;
            float z = acc[i][j] + bias[col];
            float t = tanhf(z);
            if (mode == 0) {
                out[idx] = t;                       // g_new
            } else {
                const float gv = g[idx];
                out[idx] = gv * t + (1.0f - gv) * h[idx];   // h_new
            }
        }
    }
}

// ---------------------------------------------------------------------------
// Kernel 2: o = h_new @ lin_w^T + lin_b   (M=BSZ, N=ISZ, K=HSZ)
//   lin_w is [ISZ, HSZ] row-major; dot over HSZ.
// ---------------------------------------------------------------------------
__global__ __launch_bounds__(NTHREADS) void rnn_out_gemm(
    const float* __restrict__ hn,     // [BSZ, HSZ]
    const float* __restrict__ lin_w,  // [ISZ, HSZ]
    const float* __restrict__ lin_b,  // [ISZ]
    float* __restrict__ o)            // [BSZ, ISZ]
{
    __shared__ float As[BK][BM];
    __shared__ float Bs[BK][BN + 4];   // padded: transposed scalar stores

    const int tid = threadIdx.x;
    const int tx = tid & 15;
    const int ty = tid >> 4;
    const int rowBase = blockIdx.y * BM;
    const int colBase = blockIdx.x * BN;

    float acc[TM][TN];
#pragma unroll
    for (int i = 0; i < TM; i++)
#pragma unroll
        for (int j = 0; j < TN; j++) acc[i][j] = 0.0f;

    const int aRow = tid >> 1;
    const int aK   = (tid & 1) * 4;
    const int bN   = tid >> 1;          // 0..127 (output column within tile)
    const int bK   = (tid & 1) * 4;     // 0 or 4

    for (int k0 = 0; k0 < HSZ; k0 += BK) {
        float4 av = *reinterpret_cast<const float4*>(
            &hn[(size_t)(rowBase + aRow) * HSZ + k0 + aK]);
        As[aK + 0][aRow] = av.x;
        As[aK + 1][aRow] = av.y;
        As[aK + 2][aRow] = av.z;
        As[aK + 3][aRow] = av.w;

        float4 bv = *reinterpret_cast<const float4*>(
            &lin_w[(size_t)(colBase + bN) * HSZ + k0 + bK]);
        Bs[bK + 0][bN] = bv.x;
        Bs[bK + 1][bN] = bv.y;
        Bs[bK + 2][bN] = bv.z;
        Bs[bK + 3][bN] = bv.w;

        __syncthreads();

#pragma unroll
        for (int k = 0; k < BK; k++) {
            float a[TM], b[TN];
#pragma unroll
            for (int i = 0; i < TM; i++) a[i] = As[k][ty * TM + i];
#pragma unroll
            for (int j = 0; j < TN; j++) b[j] = Bs[k][tx * TN + j];
#pragma unroll
            for (int i = 0; i < TM; i++)
#pragma unroll
                for (int j = 0; j < TN; j++)
                    acc[i][j] = fmaf(a[i], b[j], acc[i][j]);
        }
        __syncthreads();
    }

#pragma unroll
    for (int i = 0; i < TM; i++) {
        const int row = rowBase + ty * TM + i;
#pragma unroll
        for (int j = 0; j < TN; j++) {
            const int col = colBase + tx * TN + j;
            o[(size_t)row * ISZ + col] = acc[i][j] + lin_b[col];
        }
    }
}

// ---------------------------------------------------------------------------
// Launch. Inputs (metadata order):
//  0 x [B,I], 1 h [B,H], 2 g [B,H], 3 w_xh [I,H], 4 w_hh [H,H], 5 b_h [H],
//  6 w_gx [I,H], 7 w_gh [H,H], 8 b_g [H], 9 lin_w [I,H], 10 lin_b [I]
// Output: concat(o [B,I], h_new [B,H], g_new [B,H])
// ---------------------------------------------------------------------------
extern "C" void kernel_launch(void* const* d_in, const int* in_sizes, int n_in,
                              void* d_out, int out_size) {
    const float* x     = (const float*)d_in[0];
    const float* h     = (const float*)d_in[1];
    const float* g     = (const float*)d_in[2];
    const float* w_xh  = (const float*)d_in[3];
    const float* w_hh  = (const float*)d_in[4];
    const float* b_h   = (const float*)d_in[5];
    const float* w_gx  = (const float*)d_in[6];
    const float* w_gh  = (const float*)d_in[7];
    const float* b_g   = (const float*)d_in[8];
    const float* lin_w = (const float*)d_in[9];
    const float* lin_b = (const float*)d_in[10];

    float* o     = (float*)d_out;                          // [B, I]
    float* h_new = o + (size_t)BSZ * ISZ;                  // [B, H]
    float* g_new = h_new + (size_t)BSZ * HSZ;              // [B, H]

    dim3 gridGate(HSZ / BN, BSZ / BM);   // (16, 32)
    dim3 gridOut (ISZ / BN, BSZ / BM);   // (8, 32)

    // g_new = tanh(x@w_gx + h@w_gh + b_g)
    rnn_gate_gemm<<<gridGate, NTHREADS>>>(x, h, w_gx, w_gh, b_g, nullptr,
                                          g_new, 0);
    // h_new = g*tanh(x@w_xh + h@w_hh + b_h) + (1-g)*h
    rnn_gate_gemm<<<gridGate, NTHREADS>>>(x, h, w_xh, w_hh, b_h, g,
                                          h_new, 1);
    // o = h_new @ lin_w^T + lin_b
    rnn_out_gemm<<<gridOut, NTHREADS>>>(h_new, lin_w, lin_b, o);
}

// round 3
// speedup vs baseline: 1.8497x; 1.8497x over previous
#include <cuda_runtime.h>
#include <cuda_fp16.h>
#include <math.h>
#include <cstdint>

#define BSZ 4096
#define ISZ 1024
#define HSZ 2048
#define NTH 256

// ---------------------------------------------------------------------------
// Device scratch (fp16 hi/lo planes)
// ---------------------------------------------------------------------------
__device__ __half g_x_hi[BSZ * ISZ],  g_x_lo[BSZ * ISZ];
__device__ __half g_h_hi[BSZ * HSZ],  g_h_lo[BSZ * HSZ];
__device__ __half g_wgxT_hi[HSZ * ISZ], g_wgxT_lo[HSZ * ISZ];
__device__ __half g_wxhT_hi[HSZ * ISZ], g_wxhT_lo[HSZ * ISZ];
__device__ __half g_wghT_hi[HSZ * HSZ], g_wghT_lo[HSZ * HSZ];
__device__ __half g_whhT_hi[HSZ * HSZ], g_whhT_lo[HSZ * HSZ];
__device__ __half g_linw_hi[ISZ * HSZ], g_linw_lo[ISZ * HSZ];
__device__ __half g_hn_hi[BSZ * HSZ],  g_hn_lo[BSZ * HSZ];

// ---------------------------------------------------------------------------
// PTX helpers (all sm_80-era: compile for plain sm_103 target)
// ---------------------------------------------------------------------------
__device__ __forceinline__ uint32_t smem_u32(const void* p) {
    uint32_t a;
    asm("{ .reg .u64 t; cvta.to.shared.u64 t, %1; cvt.u32.u64 %0, t; }"
        : "=r"(a) : "l"(p));
    return a;
}

#define CP16(dst, src) \
    asm volatile("cp.async.cg.shared.global [%0], [%1], 16;" :: "r"(dst), "l"(src))
#define CP_COMMIT() asm volatile("cp.async.commit_group;" ::: "memory")
#define CP_WAIT0()  asm volatile("cp.async.wait_group 0;" ::: "memory")
#define CP_WAIT1()  asm volatile("cp.async.wait_group 1;" ::: "memory")

#define LDMATRIX_X4(r0, r1, r2, r3, addr)                                   \
    asm volatile("ldmatrix.sync.aligned.m8n8.x4.shared.b16 {%0,%1,%2,%3}, [%4];" \
                 : "=r"(r0), "=r"(r1), "=r"(r2), "=r"(r3) : "r"(addr))

#define MMA16816(c, a, b0, b1)                                              \
    asm volatile("mma.sync.aligned.m16n8k16.row.col.f32.f16.f16.f32 "       \
                 "{%0,%1,%2,%3}, {%4,%5,%6,%7}, {%8,%9}, {%0,%1,%2,%3};"    \
                 : "+f"((c)[0]), "+f"((c)[1]), "+f"((c)[2]), "+f"((c)[3])   \
                 : "r"((a)[0]), "r"((a)[1]), "r"((a)[2]), "r"((a)[3]),      \
                   "r"(b0), "r"(b1))

// ---------------------------------------------------------------------------
// Prep kernels: fp32 -> fp16 (hi, lo) split, optional transpose
// ---------------------------------------------------------------------------
__device__ __forceinline__ void split16(float v, __half& hi, __half& lo) {
    __half h = __float2half_rn(v);
    hi = h;
    lo = __float2half_rn(v - __half2float(h));
}

__global__ void split_kernel(const float4* __restrict__ src,
                             __half2* __restrict__ hi, __half2* __restrict__ lo,
                             int n4) {
    int i = blockIdx.x * blockDim.x + threadIdx.x;
    if (i < n4) {
        float4 v = src[i];
        __half hx, lx, hy, ly, hz, lz, hw, lw;
        split16(v.x, hx, lx); split16(v.y, hy, ly);
        split16(v.z, hz, lz); split16(v.w, hw, lw);
        hi[2 * i]     = __halves2half2(hx, hy);
        hi[2 * i + 1] = __halves2half2(hz, hw);
        lo[2 * i]     = __halves2half2(lx, ly);
        lo[2 * i + 1] = __halves2half2(lz, lw);
    }
}

// src [K,N] row-major -> dst [N,K] fp16 hi/lo
__global__ void transpose_split(const float* __restrict__ src,
                                __half* __restrict__ dhi, __half* __restrict__ dlo,
                                int K, int N) {
    __shared__ float tile[32][33];
    int nb = blockIdx.x * 32, kb = blockIdx.y * 32;
    int tx = threadIdx.x, ty = threadIdx.y;
#pragma unroll
    for (int r = 0; r < 32; r += 8)
        tile[ty + r][tx] = src[(size_t)(kb + ty + r) * N + nb + tx];
    __syncthreads();
#pragma unroll
    for (int r = 0; r < 32; r += 8) {
        float v = tile[tx][ty + r];
        __half h, l;
        split16(v, h, l);
        size_t o = (size_t)(nb + ty + r) * K + kb + tx;
        dhi[o] = h;
        dlo[o] = l;
    }
}

// ---------------------------------------------------------------------------
// Main GEMM: mma.sync m16n8k16 fp16, 3-term compensated
//   MODE 0: g_new = tanh(x@w_gx + h@w_gh + b)
//   MODE 1: h_new = g*tanh(x@w_xh + h@w_hh + b) + (1-g)*h  (+ split hn out)
//   MODE 2: o = h_new @ lin_w^T + b
// Tiles: BM=BN=128, BK=32. 8 warps, warp tile 64x32.
// SMEM row stride 40 halves (80B) -> conflict-free ldmatrix.
// ---------------------------------------------------------------------------
#define RSTRIDE 40                    // halves per smem row (32 + 8 pad)
#define TILE_BYTES (128 * RSTRIDE * 2)   // 10240
#define STAGE_BYTES (4 * TILE_BYTES)     // Ah, Al, Bh, Bl = 40960
#define NSTAGE 3
#define SMEM_MAIN (NSTAGE * STAGE_BYTES)

template <int MODE>
__global__ __launch_bounds__(NTH, 1) void gemm_f16_kernel(
    const float* __restrict__ bias,
    const float* __restrict__ graw,
    const float* __restrict__ hraw,
    float* __restrict__ out)
{
    extern __shared__ __align__(128) unsigned char dsm[];
    const uint32_t sb = smem_u32(dsm);
    const int tid = threadIdx.x;
    const int wid = tid >> 5, lane = tid & 31;
    const int rowBase = blockIdx.y * 128;
    const int colBase = blockIdx.x * 128;
    const int nchunks = (MODE == 2) ? (HSZ / 32) : ((ISZ + HSZ) / 32);
    const int ldout = (MODE == 2) ? ISZ : HSZ;

    const int wm = (wid >> 2) * 64;   // warp m offset in tile
    const int wn = (wid & 3) * 32;    // warp n offset in tile

    float acc[4][4][4];
#pragma unroll
    for (int mi = 0; mi < 4; mi++)
#pragma unroll
        for (int ni = 0; ni < 4; ni++)
#pragma unroll
            for (int q = 0; q < 4; q++) acc[mi][ni][q] = 0.0f;

    // ---- chunk loader: 4 tiles x 128 rows x 64B, cp.async 16B ----
    const int ltile = tid >> 6;       // 0 Ah, 1 Al, 2 Bh, 3 Bl
    const int lu = tid & 63;
    auto load_chunk = [&](int c) {
        const int k0 = c * 32;
        const __half *Ah, *Al, *Bh, *Bl;
        int lda, ldb, kk;
        if (MODE == 2) {
            Ah = g_hn_hi; Al = g_hn_lo; lda = HSZ; kk = k0;
            Bh = g_linw_hi; Bl = g_linw_lo; ldb = HSZ;
        } else if (k0 < ISZ) {
            Ah = g_x_hi; Al = g_x_lo; lda = ISZ; kk = k0;
            Bh = (MODE == 0) ? g_wgxT_hi : g_wxhT_hi;
            Bl = (MODE == 0) ? g_wgxT_lo : g_wxhT_lo; ldb = ISZ;
        } else {
            Ah = g_h_hi; Al = g_h_lo; lda = HSZ; kk = k0 - ISZ;
            Bh = (MODE == 0) ? g_wghT_hi : g_whhT_hi;
            Bl = (MODE == 0) ? g_wghT_lo : g_whhT_lo; ldb = HSZ;
        }
        const uint32_t base = sb + (c % NSTAGE) * STAGE_BYTES + ltile * TILE_BYTES;
        const __half* src;
        int ld, rb;
        if (ltile == 0)      { src = Ah; ld = lda; rb = rowBase; }
        else if (ltile == 1) { src = Al; ld = lda; rb = rowBase; }
        else if (ltile == 2) { src = Bh; ld = ldb; rb = colBase; }
        else                 { src = Bl; ld = ldb; rb = colBase; }
#pragma unroll
        for (int i = 0; i < 8; i++) {
            const int id = lu * 8 + i;
            const int row = id >> 2, kc = id & 3;
            CP16(base + row * (RSTRIDE * 2) + kc * 16,
                 src + (size_t)(rb + row) * ld + kk + kc * 8);
        }
        CP_COMMIT();
    };

    load_chunk(0);
    load_chunk(1);

    for (int c = 0; c < nchunks; c++) {
        if (c == nchunks - 1) { CP_WAIT0(); } else { CP_WAIT1(); }
        __syncthreads();
        if (c + 2 < nchunks) load_chunk(c + 2);

        const uint32_t base = sb + (c % NSTAGE) * STAGE_BYTES;
        const uint32_t sAh = base;
        const uint32_t sAl = base + TILE_BYTES;
        const uint32_t sBh = base + 2 * TILE_BYTES;
        const uint32_t sBl = base + 3 * TILE_BYTES;

#pragma unroll
        for (int ks = 0; ks < 2; ks++) {
            const int k = ks * 16;
            // A fragments (hi, lo): 4 m-tiles each
            const uint32_t aoff =
                (uint32_t)(wm + (lane & 15)) * (RSTRIDE * 2) +
                (uint32_t)(k + ((lane >> 4) << 3)) * 2;
            uint32_t ah[4][4], al[4][4];
#pragma unroll
            for (int mi = 0; mi < 4; mi++) {
                const uint32_t d = aoff + mi * 16 * (RSTRIDE * 2);
                LDMATRIX_X4(ah[mi][0], ah[mi][1], ah[mi][2], ah[mi][3], sAh + d);
                LDMATRIX_X4(al[mi][0], al[mi][1], al[mi][2], al[mi][3], sAl + d);
            }
            // B fragments (hi, lo): 2 n-tile pairs each (x4 = two 8-wide n tiles)
            const uint32_t boff =
                (uint32_t)(wn + ((lane >> 4) << 3) + (lane & 7)) * (RSTRIDE * 2) +
                (uint32_t)(k + (((lane >> 3) & 1) << 3)) * 2;
            uint32_t bh[2][4], bl[2][4];
#pragma unroll
            for (int np = 0; np < 2; np++) {
                const uint32_t d = boff + np * 16 * (RSTRIDE * 2);
                LDMATRIX_X4(bh[np][0], bh[np][1], bh[np][2], bh[np][3], sBh + d);
                LDMATRIX_X4(bl[np][0], bl[np][1], bl[np][2], bl[np][3], sBl + d);
            }
            // MMAs: hi*hi + hi*lo + lo*hi
#pragma unroll
            for (int mi = 0; mi < 4; mi++)
#pragma unroll
                for (int ni = 0; ni < 4; ni++) {
                    const int np = ni >> 1, q = (ni & 1) * 2;
                    MMA16816(acc[mi][ni], ah[mi], bh[np][q], bh[np][q + 1]);
                    MMA16816(acc[mi][ni], ah[mi], bl[np][q], bl[np][q + 1]);
                    MMA16816(acc[mi][ni], al[mi], bh[np][q], bh[np][q + 1]);
                }
        }
    }

    // ---- epilogue: direct register -> gmem, fused ops ----
#pragma unroll
    for (int mi = 0; mi < 4; mi++) {
#pragma unroll
        for (int ni = 0; ni < 4; ni++) {
            const int col = colBase + wn + ni * 8 + (lane & 3) * 2;
#pragma unroll
            for (int half = 0; half < 2; half++) {
                const int row = rowBase + wm + mi * 16 + (lane >> 2) + half * 8;
                const float c0 = acc[mi][ni][half * 2 + 0];
                const float c1 = acc[mi][ni][half * 2 + 1];
                const size_t oidx = (size_t)row * ldout + col;
                if (MODE == 0) {
                    float2 r;
                    r.x = tanhf(c0 + bias[col]);
                    r.y = tanhf(c1 + bias[col + 1]);
                    *(float2*)&out[oidx] = r;
                } else if (MODE == 1) {
                    const size_t ii = (size_t)row * HSZ + col;
                    const float2 gv = *(const float2*)&graw[ii];
                    const float2 hv = *(const float2*)&hraw[ii];
                    const float t0 = tanhf(c0 + bias[col]);
                    const float t1 = tanhf(c1 + bias[col + 1]);
                    float2 hn;
                    hn.x = gv.x * t0 + (1.0f - gv.x) * hv.x;
                    hn.y = gv.y * t1 + (1.0f - gv.y) * hv.y;
                    *(float2*)&out[oidx] = hn;
                    __half h0, l0, h1, l1;
                    split16(hn.x, h0, l0);
                    split16(hn.y, h1, l1);
                    *(__half2*)&g_hn_hi[ii] = __halves2half2(h0, h1);
                    *(__half2*)&g_hn_lo[ii] = __halves2half2(l0, l1);
                } else {
                    float2 r;
                    r.x = c0 + bias[col];
                    r.y = c1 + bias[col + 1];
                    *(float2*)&out[oidx] = r;
                }
            }
        }
    }
}

// ---------------------------------------------------------------------------
// Launch
// ---------------------------------------------------------------------------
extern "C" void kernel_launch(void* const* d_in, const int* in_sizes, int n_in,
                              void* d_out, int out_size) {
    const float* x     = (const float*)d_in[0];
    const float* h     = (const float*)d_in[1];
    const float* g     = (const float*)d_in[2];
    const float* w_xh  = (const float*)d_in[3];
    const float* w_hh  = (const float*)d_in[4];
    const float* b_h   = (const float*)d_in[5];
    const float* w_gx  = (const float*)d_in[6];
    const float* w_gh  = (const float*)d_in[7];
    const float* b_g   = (const float*)d_in[8];
    const float* lin_w = (const float*)d_in[9];
    const float* lin_b = (const float*)d_in[10];

    float* o     = (float*)d_out;
    float* h_new = o + (size_t)BSZ * ISZ;
    float* g_new = h_new + (size_t)BSZ * HSZ;

    void *xh, *xl, *hh, *hl, *lh, *ll;
    void *gxh, *gxl, *ghh, *ghl, *xhh, *xhl, *hhh, *hhl;
    cudaGetSymbolAddress(&xh, g_x_hi);    cudaGetSymbolAddress(&xl, g_x_lo);
    cudaGetSymbolAddress(&hh, g_h_hi);    cudaGetSymbolAddress(&hl, g_h_lo);
    cudaGetSymbolAddress(&lh, g_linw_hi); cudaGetSymbolAddress(&ll, g_linw_lo);
    cudaGetSymbolAddress(&gxh, g_wgxT_hi); cudaGetSymbolAddress(&gxl, g_wgxT_lo);
    cudaGetSymbolAddress(&ghh, g_wghT_hi); cudaGetSymbolAddress(&ghl, g_wghT_lo);
    cudaGetSymbolAddress(&xhh, g_wxhT_hi); cudaGetSymbolAddress(&xhl, g_wxhT_lo);
    cudaGetSymbolAddress(&hhh, g_whhT_hi); cudaGetSymbolAddress(&hhl, g_whhT_lo);

    cudaFuncSetAttribute(gemm_f16_kernel<0>, cudaFuncAttributeMaxDynamicSharedMemorySize, SMEM_MAIN);
    cudaFuncSetAttribute(gemm_f16_kernel<1>, cudaFuncAttributeMaxDynamicSharedMemorySize, SMEM_MAIN);
    cudaFuncSetAttribute(gemm_f16_kernel<2>, cudaFuncAttributeMaxDynamicSharedMemorySize, SMEM_MAIN);

    // fp16 hi/lo splits (no transpose)
    split_kernel<<<(BSZ * ISZ / 4 + 255) / 256, 256>>>((const float4*)x, (__half2*)xh, (__half2*)xl, BSZ * ISZ / 4);
    split_kernel<<<(BSZ * HSZ / 4 + 255) / 256, 256>>>((const float4*)h, (__half2*)hh, (__half2*)hl, BSZ * HSZ / 4);
    split_kernel<<<(ISZ * HSZ / 4 + 255) / 256, 256>>>((const float4*)lin_w, (__half2*)lh, (__half2*)ll, ISZ * HSZ / 4);

    // weight transposes + splits ([K,N] -> [N,K])
    transpose_split<<<dim3(HSZ / 32, ISZ / 32), dim3(32, 8)>>>(w_gx, (__half*)gxh, (__half*)gxl, ISZ, HSZ);
    transpose_split<<<dim3(HSZ / 32, HSZ / 32), dim3(32, 8)>>>(w_gh, (__half*)ghh, (__half*)ghl, HSZ, HSZ);
    transpose_split<<<dim3(HSZ / 32, ISZ / 32), dim3(32, 8)>>>(w_xh, (__half*)xhh, (__half*)xhl, ISZ, HSZ);
    transpose_split<<<dim3(HSZ / 32, HSZ / 32), dim3(32, 8)>>>(w_hh, (__half*)hhh, (__half*)hhl, HSZ, HSZ);

    // GEMMs
    gemm_f16_kernel<0><<<dim3(HSZ / 128, BSZ / 128), NTH, SMEM_MAIN>>>(b_g, nullptr, nullptr, g_new);
    gemm_f16_kernel<1><<<dim3(HSZ / 128, BSZ / 128), NTH, SMEM_MAIN>>>(b_h, g, h, h_new);
    gemm_f16_kernel<2><<<dim3(ISZ / 128, BSZ / 128), NTH, SMEM_MAIN>>>(lin_b, nullptr, nullptr, o);
}